// round 10
// baseline (speedup 1.0000x reference)
#include <cuda_runtime.h>
#include <cuda_bf16.h>
#include <math.h>
#include <stdint.h>

// Problem constants
#define B_    256
#define S_    20
#define V_    20000
#define C_    20
#define D_    64
#define SUPROWS 5120          // B_*S_ = 40*128 -> tiles never straddle sup/tgt
#define MROWS   5376          // SUPROWS + B_
#define KSPLIT  7
#define NCHUNK  313           // ceil(20000/64); last chunk has 32 valid k
#define TILE_R  128

// Scratch (allocation-free rule: __device__ globals)
__device__ float g_Yp[KSPLIT * MROWS * D_];   // K-split partial projections
__device__ float g_res[2 * B_];               // per-batch (correct, loss)
__device__ int   g_cnt = 0;                   // head-block completion counter

// ---- smem layout (dynamic), per buffer: A_hi 16K | A_lo 16K | W_hi 8K | W_lo 8K
#define BUF_STRIDE 49152
#define A_HI_OFF   0
#define A_LO_OFF   16384
#define W_HI_OFF   32768
#define W_LO_OFF   40960
#define SMEM_TOTAL (2 * BUF_STRIDE)

__device__ __forceinline__ uint32_t smem_u32(const void* p) {
    uint32_t a;
    asm("{ .reg .u64 t; cvta.to.shared.u64 t, %1; cvt.u32.u64 %0, t; }" : "=r"(a) : "l"(p));
    return a;
}
// hi-pack: bf16x2 from truncated top halves of two f32 (low elem from a)
__device__ __forceinline__ uint32_t prmt_hi(float a, float b) {
    uint32_t r;
    asm("prmt.b32 %0, %1, %2, 0x7632;" : "=r"(r) : "r"(__float_as_uint(a)), "r"(__float_as_uint(b)));
    return r;
}
__device__ __forceinline__ float trunc_hi(float x) {
    return __uint_as_float(__float_as_uint(x) & 0xffff0000u);
}
// lo-pack: bf16x2 rn of residuals; low elem from a
__device__ __forceinline__ uint32_t pack_lo(float a, float b) {
    float la = a - trunc_hi(a);
    float lb = b - trunc_hi(b);
    uint32_t r;
    asm("cvt.rn.bf16x2.f32 %0, %1, %2;" : "=r"(r) : "f"(lb), "f"(la));
    return r;
}
__device__ __forceinline__ void ldsm4(uint32_t* r, uint32_t addr) {
    asm volatile("ldmatrix.sync.aligned.m8n8.x4.shared.b16 {%0,%1,%2,%3}, [%4];"
                 : "=r"(r[0]), "=r"(r[1]), "=r"(r[2]), "=r"(r[3]) : "r"(addr));
}
__device__ __forceinline__ void mma_bf16(float* d, const uint32_t* a, const uint32_t* b) {
    asm volatile(
        "mma.sync.aligned.m16n8k16.row.col.f32.bf16.bf16.f32 "
        "{%0,%1,%2,%3}, {%4,%5,%6,%7}, {%8,%9}, {%0,%1,%2,%3};"
        : "+f"(d[0]), "+f"(d[1]), "+f"(d[2]), "+f"(d[3])
        : "r"(a[0]), "r"(a[1]), "r"(a[2]), "r"(a[3]), "r"(b[0]), "r"(b[1]));
}

// staged bf16 row layout: 128B per row, 8B granules XOR-swizzled by (row&7)
__device__ __forceinline__ uint32_t stage_addr(int row, int k4) {
    return (uint32_t)((row << 7) | ((((k4 >> 1) ^ (row & 7)) << 4) | ((k4 & 1) << 3)));
}

// ---------------------------------------------------------------------------
// GEMM via HMMA bf16-split (hi*hi + lo*hi + hi*lo), fp32 register accumulate.
// Tile 128 x 64; K chunks of 64; 8 warps each own 32r x 32c.
// Per kstep: ldsm(Ah,Bh,Al) -> hh mmas -> ldsm(Bl) -> lh mmas -> hl mmas,
// so every mma pass consumes data loaded at least one pass earlier.
// ---------------------------------------------------------------------------
__global__ __launch_bounds__(256, 2)
void gemm_kernel(const float* __restrict__ sup,
                 const float* __restrict__ tgt,
                 const float* __restrict__ W) {
    extern __shared__ char smem[];
    const uint32_t sb = smem_u32(smem);
    const int tid = threadIdx.x;
    const int wid = tid >> 5;
    const int lane = tid & 31;
    const int wr = wid >> 1;          // warp row group: rows 32*wr
    const int wc = wid & 1;           // warp col group: cols 32*wc
    const int rowbase = blockIdx.x * TILE_R;
    const int by = blockIdx.y;

    const int c0 = (by * NCHUNK) / KSPLIT;
    const int c1 = ((by + 1) * NCHUNK) / KSPLIT;
    const int n = c1 - c0;

    // --- loader mapping: single base ptr (tiles never straddle sup/tgt) ---
    const float* abase = (rowbase < SUPROWS)
                         ? (sup + (size_t)rowbase * V_)
                         : (tgt + (size_t)(rowbase - SUPROWS) * V_);
    const int a_k4 = tid & 15;        // float4 index within 64-k chunk
    const int lrow0 = tid >> 4;       // base loader row (0..15)
    const int kofs = 4 * a_k4;

    // per-wave STS addresses (4 A rows + 2 W rows per wave)
    uint32_t a_sts[8], w_sts[4];
    #pragma unroll
    for (int i = 0; i < 8; ++i) a_sts[i] = stage_addr(lrow0 + 16 * i, a_k4);
    #pragma unroll
    for (int i = 0; i < 4; ++i) w_sts[i] = stage_addr(lrow0 + 16 * i, a_k4);

    // --- ldmatrix per-thread address precompute ---
    const int quad = lane >> 3;
    const int rin = lane & 7;
    uint32_t arow128[2], asw[2];
    #pragma unroll
    for (int m = 0; m < 2; ++m) {
        int row = 32 * wr + 16 * m + (quad & 1) * 8 + rin;
        arow128[m] = (uint32_t)(row << 7);
        asw[m] = (uint32_t)((row & 7) << 4);
    }
    const uint32_t acolq = (uint32_t)((quad >> 1) << 4);
    uint32_t brow128[2], bsw[2];
    #pragma unroll
    for (int p = 0; p < 2; ++p) {
        int row = 32 * wc + 16 * p + (quad >> 1) * 8 + rin;
        brow128[p] = (uint32_t)(row << 7);
        bsw[p] = (uint32_t)((row & 7) << 4);
    }
    const uint32_t bcolq = (uint32_t)((quad & 1) << 4);

    float acc[2][4][4];
    #pragma unroll
    for (int m = 0; m < 2; ++m)
        #pragma unroll
        for (int g = 0; g < 4; ++g)
            #pragma unroll
            for (int j = 0; j < 4; ++j) acc[m][g][j] = 0.f;

    const float4 z4 = make_float4(0.f, 0.f, 0.f, 0.f);
    float4 pfA[4], pfW[2];            // one-wave prefetch registers (reused)

    // load wave w (w=0: A rows 0-63, W rows 0-31; w=1: A 64-127, W 32-63)
    auto load_wave = [&](int kbase, int w) {
        const bool v = (kbase + kofs + 3 < V_);
        const size_t kb = (size_t)(kbase + kofs);
        #pragma unroll
        for (int i = 0; i < 4; ++i) {
            const int r = lrow0 + 16 * (4 * w + i);
            pfA[i] = v ? *(const float4*)(abase + (size_t)r * V_ + kb) : z4;
        }
        #pragma unroll
        for (int i = 0; i < 2; ++i) {
            const int r = lrow0 + 16 * (2 * w + i);
            pfW[i] = v ? *(const float4*)(W + (size_t)r * V_ + kb) : z4;
        }
    };
    // stage wave w into buffer base
    auto stage_wave = [&](char* base, int w) {
        #pragma unroll
        for (int i = 0; i < 4; ++i) {
            float4 p = pfA[i];
            uint32_t h0 = prmt_hi(p.x, p.y), h1 = prmt_hi(p.z, p.w);
            uint32_t l0 = pack_lo(p.x, p.y), l1 = pack_lo(p.z, p.w);
            const uint32_t o = a_sts[4 * w + i];
            *(uint2*)(base + A_HI_OFF + o) = make_uint2(h0, h1);
            *(uint2*)(base + A_LO_OFF + o) = make_uint2(l0, l1);
        }
        #pragma unroll
        for (int i = 0; i < 2; ++i) {
            float4 p = pfW[i];
            uint32_t h0 = prmt_hi(p.x, p.y), h1 = prmt_hi(p.z, p.w);
            uint32_t l0 = pack_lo(p.x, p.y), l1 = pack_lo(p.z, p.w);
            const uint32_t o = w_sts[2 * w + i];
            *(uint2*)(base + W_HI_OFF + o) = make_uint2(h0, h1);
            *(uint2*)(base + W_LO_OFF + o) = make_uint2(l0, l1);
        }
    };
    // compute 2 ksteps; ldsm/mma interleaved so each pass's operands were
    // loaded at least one mma-pass earlier (latency covered by ~8 mmas)
    auto compute2 = [&](uint32_t bufb, int ks0) {
        const uint32_t abh = bufb + A_HI_OFF, abl = bufb + A_LO_OFF;
        const uint32_t wbh = bufb + W_HI_OFF, wbl = bufb + W_LO_OFF;
        #pragma unroll
        for (int ks = ks0; ks < ks0 + 2; ++ks) {
            const uint32_t ac = (uint32_t)(32 * ks) + acolq;
            const uint32_t bc = (uint32_t)(32 * ks) + bcolq;
            uint32_t Ah[2][4], Al[2][4], Bh[2][4], Bl[2][4];
            // operands for the hh pass first
            ldsm4(Ah[0], abh + arow128[0] + (ac ^ asw[0]));
            ldsm4(Ah[1], abh + arow128[1] + (ac ^ asw[1]));
            ldsm4(Bh[0], wbh + brow128[0] + (bc ^ bsw[0]));
            ldsm4(Bh[1], wbh + brow128[1] + (bc ^ bsw[1]));
            // Al issued now; consumed only in the lh pass (after 8 hh mmas)
            ldsm4(Al[0], abl + arow128[0] + (ac ^ asw[0]));
            ldsm4(Al[1], abl + arow128[1] + (ac ^ asw[1]));
            #pragma unroll
            for (int m = 0; m < 2; ++m)
                #pragma unroll
                for (int g = 0; g < 4; ++g)
                    mma_bf16(acc[m][g], Ah[m], &Bh[g >> 1][(g & 1) * 2]);
            // Bl issued now; consumed only in the hl pass (after 8 lh mmas)
            ldsm4(Bl[0], wbl + brow128[0] + (bc ^ bsw[0]));
            ldsm4(Bl[1], wbl + brow128[1] + (bc ^ bsw[1]));
            #pragma unroll
            for (int m = 0; m < 2; ++m)
                #pragma unroll
                for (int g = 0; g < 4; ++g)
                    mma_bf16(acc[m][g], Al[m], &Bh[g >> 1][(g & 1) * 2]);
            #pragma unroll
            for (int m = 0; m < 2; ++m)
                #pragma unroll
                for (int g = 0; g < 4; ++g)
                    mma_bf16(acc[m][g], Ah[m], &Bl[g >> 1][(g & 1) * 2]);
        }
    };

    // --- prologue: stage chunk c0 into buf0 (two waves, reusing regs) ---
    load_wave(c0 * 64, 0);
    stage_wave(smem, 0);
    load_wave(c0 * 64, 1);
    stage_wave(smem, 1);
    __syncthreads();

    for (int i = 0; i < n; ++i) {
        const bool more = (i + 1 < n);
        const int kb2 = (c0 + i + 1) * 64;
        const uint32_t bufb = sb + (uint32_t)((i & 1) * BUF_STRIDE);
        char* nbuf = smem + ((i + 1) & 1) * BUF_STRIDE;

        if (more) load_wave(kb2, 0);
        compute2(bufb, 0);
        if (more) {
            stage_wave(nbuf, 0);
            load_wave(kb2, 1);
        }
        compute2(bufb, 2);
        if (more) {
            stage_wave(nbuf, 1);
            __syncthreads();
        }
    }

    // --- epilogue: acc -> g_Yp ---
    float* yp = g_Yp + ((size_t)by * MROWS + rowbase) * D_;
    #pragma unroll
    for (int m = 0; m < 2; ++m) {
        const int r0 = 32 * wr + 16 * m + (lane >> 2);
        #pragma unroll
        for (int g = 0; g < 4; ++g) {
            const int nn = 32 * wc + 8 * g + 2 * (lane & 3);
            *(float2*)(yp + (size_t)r0 * D_ + nn) =
                make_float2(acc[m][g][0], acc[m][g][1]);
            *(float2*)(yp + (size_t)(r0 + 8) * D_ + nn) =
                make_float2(acc[m][g][2], acc[m][g][3]);
        }
    }
}

// ---------------------------------------------------------------------------
// Head: one warp per batch element; the last block to finish also performs
// the final deterministic reduction and writes d_out (no separate kernel).
// ---------------------------------------------------------------------------
__global__ __launch_bounds__(32)
void head_kernel(const float* __restrict__ onehot,
                 const int* __restrict__ tylab,
                 const float* __restrict__ bias,
                 float* __restrict__ out) {
    const int b = blockIdx.x;
    const int lane = threadIdx.x;
    const unsigned FULL = 0xffffffffu;

    const float b0 = bias[lane], b1 = bias[lane + 32];

    const int trow = SUPROWS + b;
    float tg0 = b0, tg1 = b1;
    #pragma unroll
    for (int p = 0; p < KSPLIT; ++p) {
        const float* r = g_Yp + ((size_t)p * MROWS + trow) * D_;
        tg0 += r[lane]; tg1 += r[lane + 32];
    }

    float sims[S_];
    #pragma unroll
    for (int s = 0; s < S_; ++s) {
        const int row = b * S_ + s;
        float v0 = b0, v1 = b1;
        #pragma unroll
        for (int p = 0; p < KSPLIT; ++p) {
            const float* r = g_Yp + ((size_t)p * MROWS + row) * D_;
            v0 += r[lane]; v1 += r[lane + 32];
        }
        float dot = v0 * tg0 + v1 * tg1;
        float nrm = v0 * v0 + v1 * v1;
        #pragma unroll
        for (int o = 16; o > 0; o >>= 1) {
            dot += __shfl_xor_sync(FULL, dot, o);
            nrm += __shfl_xor_sync(FULL, nrm, o);
        }
        sims[s] = dot * rsqrtf(fmaxf(nrm, 1e-10f));
    }

    float m = sims[0];
    #pragma unroll
    for (int s = 1; s < S_; ++s) m = fmaxf(m, sims[s]);
    float e[S_];
    float den = 0.f;
    #pragma unroll
    for (int s = 0; s < S_; ++s) { e[s] = expf(sims[s] - m); den += e[s]; }
    const float inv = 1.f / den;

    float pred = 0.f;
    if (lane < C_) {
        #pragma unroll
        for (int s = 0; s < S_; ++s)
            pred += e[s] * inv * onehot[((size_t)b * S_ + s) * C_ + lane];
    }

    float pv = (lane < C_) ? pred : -3.0e38f;
    float pm = pv;
    #pragma unroll
    for (int o = 16; o > 0; o >>= 1) pm = fmaxf(pm, __shfl_xor_sync(FULL, pm, o));
    float ex = (lane < C_) ? expf(pred - pm) : 0.f;
    float se = ex;
    #pragma unroll
    for (int o = 16; o > 0; o >>= 1) se += __shfl_xor_sync(FULL, se, o);
    const float lse = pm + logf(se);

    float av = pv;
    int ai = lane;
    #pragma unroll
    for (int o = 16; o > 0; o >>= 1) {
        float ov = __shfl_xor_sync(FULL, av, o);
        int oi = __shfl_xor_sync(FULL, ai, o);
        if (ov > av || (ov == av && oi < ai)) { av = ov; ai = oi; }
    }

    const int t = tylab[b];
    const float pt = __shfl_sync(FULL, pred, t);
    if (lane == 0) {
        g_res[b] = (ai == t) ? 1.f : 0.f;
        g_res[B_ + b] = -(pt - lse);
    }

    // --- last block does the final reduction (deterministic fixed order) ---
    __threadfence();
    int old = 0;
    if (lane == 0) old = atomicAdd(&g_cnt, 1);
    old = __shfl_sync(FULL, old, 0);
    if (old == B_ - 1) {
        __threadfence();
        float s0 = 0.f, s1 = 0.f;
        #pragma unroll
        for (int j = 0; j < B_ / 32; ++j) {     // lane-sequential fixed order
            s0 += g_res[lane + 32 * j];
            s1 += g_res[B_ + lane + 32 * j];
        }
        #pragma unroll
        for (int o = 16; o > 0; o >>= 1) {
            s0 += __shfl_xor_sync(FULL, s0, o);
            s1 += __shfl_xor_sync(FULL, s1, o);
        }
        if (lane == 0) {
            out[0] = s0 * (1.f / B_);
            out[1] = s1 * (1.f / B_);
            __threadfence();
            g_cnt = 0;                          // reset for next launch/replay
        }
    }
}

extern "C" void kernel_launch(void* const* d_in, const int* in_sizes, int n_in,
                              void* d_out, int out_size) {
    const float* sup    = (const float*)d_in[0];
    const float* onehot = (const float*)d_in[1];
    const float* tgt    = (const float*)d_in[2];
    const int*   tylab  = (const int*)d_in[3];
    const float* W      = (const float*)d_in[4];
    const float* bias   = (const float*)d_in[5];
    (void)in_sizes; (void)n_in; (void)out_size;

    cudaFuncSetAttribute(gemm_kernel,
                         cudaFuncAttributeMaxDynamicSharedMemorySize, SMEM_TOTAL);

    dim3 grid(MROWS / TILE_R, KSPLIT);
    gemm_kernel<<<grid, 256, SMEM_TOTAL>>>(sup, tgt, W);
    head_kernel<<<B_, 32>>>(onehot, tylab, bias, (float*)d_out);
}

// round 11
// speedup vs baseline: 1.0622x; 1.0622x over previous
#include <cuda_runtime.h>
#include <cuda_bf16.h>
#include <math.h>
#include <stdint.h>

// Problem constants
#define B_    256
#define S_    20
#define V_    20000
#define C_    20
#define D_    64
#define SUPROWS 5120          // B_*S_ = 40*128 -> tiles never straddle sup/tgt
#define MROWS   5376          // SUPROWS + B_
#define KSPLIT  7
#define NCHUNK  313           // ceil(20000/64); last chunk has 32 valid k
#define TILE_R  128

// Scratch (allocation-free rule: __device__ globals)
__device__ float g_Yp[KSPLIT * MROWS * D_];   // K-split partial projections
__device__ float g_res[2 * B_];               // per-batch (correct, loss)

// ---- smem layout (dynamic), per buffer: A_hi 16K | A_lo 16K | W_hi 8K | W_lo 8K
#define BUF_STRIDE 49152
#define A_HI_OFF   0
#define A_LO_OFF   16384
#define W_HI_OFF   32768
#define W_LO_OFF   40960
#define SMEM_TOTAL (2 * BUF_STRIDE)

__device__ __forceinline__ uint32_t smem_u32(const void* p) {
    uint32_t a;
    asm("{ .reg .u64 t; cvta.to.shared.u64 t, %1; cvt.u32.u64 %0, t; }" : "=r"(a) : "l"(p));
    return a;
}
// hi-pack: bf16x2 from truncated top halves of two f32 (low elem from a)
__device__ __forceinline__ uint32_t prmt_hi(float a, float b) {
    uint32_t r;
    asm("prmt.b32 %0, %1, %2, 0x7632;" : "=r"(r) : "r"(__float_as_uint(a)), "r"(__float_as_uint(b)));
    return r;
}
__device__ __forceinline__ float trunc_hi(float x) {
    return __uint_as_float(__float_as_uint(x) & 0xffff0000u);
}
// lo-pack: bf16x2 rn of residuals; low elem from a
__device__ __forceinline__ uint32_t pack_lo(float a, float b) {
    float la = a - trunc_hi(a);
    float lb = b - trunc_hi(b);
    uint32_t r;
    asm("cvt.rn.bf16x2.f32 %0, %1, %2;" : "=r"(r) : "f"(lb), "f"(la));
    return r;
}
__device__ __forceinline__ void ldsm4(uint32_t* r, uint32_t addr) {
    asm volatile("ldmatrix.sync.aligned.m8n8.x4.shared.b16 {%0,%1,%2,%3}, [%4];"
                 : "=r"(r[0]), "=r"(r[1]), "=r"(r[2]), "=r"(r[3]) : "r"(addr));
}
__device__ __forceinline__ void mma_bf16(float* d, const uint32_t* a, const uint32_t* b) {
    asm volatile(
        "mma.sync.aligned.m16n8k16.row.col.f32.bf16.bf16.f32 "
        "{%0,%1,%2,%3}, {%4,%5,%6,%7}, {%8,%9}, {%0,%1,%2,%3};"
        : "+f"(d[0]), "+f"(d[1]), "+f"(d[2]), "+f"(d[3])
        : "r"(a[0]), "r"(a[1]), "r"(a[2]), "r"(a[3]), "r"(b[0]), "r"(b[1]));
}

// staged bf16 row layout: 128B per row, 8B granules XOR-swizzled by (row&7)
__device__ __forceinline__ uint32_t stage_addr(int row, int k4) {
    return (uint32_t)((row << 7) | ((((k4 >> 1) ^ (row & 7)) << 4) | ((k4 & 1) << 3)));
}

// ---------------------------------------------------------------------------
// GEMM via HMMA bf16-split (hi*hi + lo*hi + hi*lo), fp32 register accumulate.
// Tile 128 x 64; K chunks of 64; 8 warps each own 32r x 32c.
// Per kstep: ldsm(Ah,Bh,Al) -> hh mmas -> ldsm(Bl) -> lh mmas -> hl mmas.
// ---------------------------------------------------------------------------
__global__ __launch_bounds__(256, 2)
void gemm_kernel(const float* __restrict__ sup,
                 const float* __restrict__ tgt,
                 const float* __restrict__ W) {
    extern __shared__ char smem[];
    const uint32_t sb = smem_u32(smem);
    const int tid = threadIdx.x;
    const int wid = tid >> 5;
    const int lane = tid & 31;
    const int wr = wid >> 1;          // warp row group: rows 32*wr
    const int wc = wid & 1;           // warp col group: cols 32*wc
    const int rowbase = blockIdx.x * TILE_R;
    const int by = blockIdx.y;

    const int c0 = (by * NCHUNK) / KSPLIT;
    const int c1 = ((by + 1) * NCHUNK) / KSPLIT;
    const int n = c1 - c0;

    // --- loader mapping: single base ptr (tiles never straddle sup/tgt) ---
    const float* abase = (rowbase < SUPROWS)
                         ? (sup + (size_t)rowbase * V_)
                         : (tgt + (size_t)(rowbase - SUPROWS) * V_);
    const int a_k4 = tid & 15;        // float4 index within 64-k chunk
    const int lrow0 = tid >> 4;       // base loader row (0..15)
    const int kofs = 4 * a_k4;

    // per-wave STS addresses (4 A rows + 2 W rows per wave)
    uint32_t a_sts[8], w_sts[4];
    #pragma unroll
    for (int i = 0; i < 8; ++i) a_sts[i] = stage_addr(lrow0 + 16 * i, a_k4);
    #pragma unroll
    for (int i = 0; i < 4; ++i) w_sts[i] = stage_addr(lrow0 + 16 * i, a_k4);

    // --- ldmatrix per-thread address precompute ---
    const int quad = lane >> 3;
    const int rin = lane & 7;
    uint32_t arow128[2], asw[2];
    #pragma unroll
    for (int m = 0; m < 2; ++m) {
        int row = 32 * wr + 16 * m + (quad & 1) * 8 + rin;
        arow128[m] = (uint32_t)(row << 7);
        asw[m] = (uint32_t)((row & 7) << 4);
    }
    const uint32_t acolq = (uint32_t)((quad >> 1) << 4);
    uint32_t brow128[2], bsw[2];
    #pragma unroll
    for (int p = 0; p < 2; ++p) {
        int row = 32 * wc + 16 * p + (quad >> 1) * 8 + rin;
        brow128[p] = (uint32_t)(row << 7);
        bsw[p] = (uint32_t)((row & 7) << 4);
    }
    const uint32_t bcolq = (uint32_t)((quad & 1) << 4);

    float acc[2][4][4];
    #pragma unroll
    for (int m = 0; m < 2; ++m)
        #pragma unroll
        for (int g = 0; g < 4; ++g)
            #pragma unroll
            for (int j = 0; j < 4; ++j) acc[m][g][j] = 0.f;

    const float4 z4 = make_float4(0.f, 0.f, 0.f, 0.f);
    float4 pfA[4], pfW[2];            // one-wave prefetch registers (reused)

    // load wave w (w=0: A rows 0-63, W rows 0-31; w=1: A 64-127, W 32-63)
    auto load_wave = [&](int kbase, int w) {
        const bool v = (kbase + kofs + 3 < V_);
        const size_t kb = (size_t)(kbase + kofs);
        #pragma unroll
        for (int i = 0; i < 4; ++i) {
            const int r = lrow0 + 16 * (4 * w + i);
            pfA[i] = v ? *(const float4*)(abase + (size_t)r * V_ + kb) : z4;
        }
        #pragma unroll
        for (int i = 0; i < 2; ++i) {
            const int r = lrow0 + 16 * (2 * w + i);
            pfW[i] = v ? *(const float4*)(W + (size_t)r * V_ + kb) : z4;
        }
    };
    // stage wave w into buffer base
    auto stage_wave = [&](char* base, int w) {
        #pragma unroll
        for (int i = 0; i < 4; ++i) {
            float4 p = pfA[i];
            uint32_t h0 = prmt_hi(p.x, p.y), h1 = prmt_hi(p.z, p.w);
            uint32_t l0 = pack_lo(p.x, p.y), l1 = pack_lo(p.z, p.w);
            const uint32_t o = a_sts[4 * w + i];
            *(uint2*)(base + A_HI_OFF + o) = make_uint2(h0, h1);
            *(uint2*)(base + A_LO_OFF + o) = make_uint2(l0, l1);
        }
        #pragma unroll
        for (int i = 0; i < 2; ++i) {
            float4 p = pfW[i];
            uint32_t h0 = prmt_hi(p.x, p.y), h1 = prmt_hi(p.z, p.w);
            uint32_t l0 = pack_lo(p.x, p.y), l1 = pack_lo(p.z, p.w);
            const uint32_t o = w_sts[2 * w + i];
            *(uint2*)(base + W_HI_OFF + o) = make_uint2(h0, h1);
            *(uint2*)(base + W_LO_OFF + o) = make_uint2(l0, l1);
        }
    };
    // compute 2 ksteps; ldsm/mma interleaved so each pass's operands were
    // loaded at least one mma-pass earlier
    auto compute2 = [&](uint32_t bufb, int ks0) {
        const uint32_t abh = bufb + A_HI_OFF, abl = bufb + A_LO_OFF;
        const uint32_t wbh = bufb + W_HI_OFF, wbl = bufb + W_LO_OFF;
        #pragma unroll
        for (int ks = ks0; ks < ks0 + 2; ++ks) {
            const uint32_t ac = (uint32_t)(32 * ks) + acolq;
            const uint32_t bc = (uint32_t)(32 * ks) + bcolq;
            uint32_t Ah[2][4], Al[2][4], Bh[2][4], Bl[2][4];
            ldsm4(Ah[0], abh + arow128[0] + (ac ^ asw[0]));
            ldsm4(Ah[1], abh + arow128[1] + (ac ^ asw[1]));
            ldsm4(Bh[0], wbh + brow128[0] + (bc ^ bsw[0]));
            ldsm4(Bh[1], wbh + brow128[1] + (bc ^ bsw[1]));
            ldsm4(Al[0], abl + arow128[0] + (ac ^ asw[0]));
            ldsm4(Al[1], abl + arow128[1] + (ac ^ asw[1]));
            #pragma unroll
            for (int m = 0; m < 2; ++m)
                #pragma unroll
                for (int g = 0; g < 4; ++g)
                    mma_bf16(acc[m][g], Ah[m], &Bh[g >> 1][(g & 1) * 2]);
            ldsm4(Bl[0], wbl + brow128[0] + (bc ^ bsw[0]));
            ldsm4(Bl[1], wbl + brow128[1] + (bc ^ bsw[1]));
            #pragma unroll
            for (int m = 0; m < 2; ++m)
                #pragma unroll
                for (int g = 0; g < 4; ++g)
                    mma_bf16(acc[m][g], Al[m], &Bh[g >> 1][(g & 1) * 2]);
            #pragma unroll
            for (int m = 0; m < 2; ++m)
                #pragma unroll
                for (int g = 0; g < 4; ++g)
                    mma_bf16(acc[m][g], Ah[m], &Bl[g >> 1][(g & 1) * 2]);
        }
    };

    // --- prologue: stage chunk c0 into buf0 (two waves, reusing regs) ---
    load_wave(c0 * 64, 0);
    stage_wave(smem, 0);
    load_wave(c0 * 64, 1);
    stage_wave(smem, 1);
    __syncthreads();

    for (int i = 0; i < n; ++i) {
        const bool more = (i + 1 < n);
        const int kb2 = (c0 + i + 1) * 64;
        const uint32_t bufb = sb + (uint32_t)((i & 1) * BUF_STRIDE);
        char* nbuf = smem + ((i + 1) & 1) * BUF_STRIDE;

        if (more) load_wave(kb2, 0);
        compute2(bufb, 0);
        if (more) {
            stage_wave(nbuf, 0);
            load_wave(kb2, 1);
        }
        compute2(bufb, 2);
        if (more) {
            stage_wave(nbuf, 1);
            __syncthreads();
        }
    }

    // --- epilogue: acc -> g_Yp ---
    float* yp = g_Yp + ((size_t)by * MROWS + rowbase) * D_;
    #pragma unroll
    for (int m = 0; m < 2; ++m) {
        const int r0 = 32 * wr + 16 * m + (lane >> 2);
        #pragma unroll
        for (int g = 0; g < 4; ++g) {
            const int nn = 32 * wc + 8 * g + 2 * (lane & 3);
            *(float2*)(yp + (size_t)r0 * D_ + nn) =
                make_float2(acc[m][g][0], acc[m][g][1]);
            *(float2*)(yp + (size_t)(r0 + 8) * D_ + nn) =
                make_float2(acc[m][g][2], acc[m][g][3]);
        }
    }
}

// ---------------------------------------------------------------------------
// Head: one block (4 warps) per batch element. Warp w computes support items
// s in {w, w+4, ..., w+16}; sims exchanged via smem; warp 0 does softmax/
// preds/argmax/loss.
// ---------------------------------------------------------------------------
__global__ __launch_bounds__(128)
void head_kernel(const float* __restrict__ onehot,
                 const int* __restrict__ tylab,
                 const float* __restrict__ bias) {
    const int b = blockIdx.x;
    const int lane = threadIdx.x & 31;
    const int w = threadIdx.x >> 5;
    const unsigned FULL = 0xffffffffu;

    __shared__ float sims_sh[S_];

    const float b0 = bias[lane], b1 = bias[lane + 32];

    // target embedding (2 dims per lane; all warps redundantly)
    const int trow = SUPROWS + b;
    float tg0 = b0, tg1 = b1;
    #pragma unroll
    for (int p = 0; p < KSPLIT; ++p) {
        const float* r = g_Yp + ((size_t)p * MROWS + trow) * D_;
        tg0 += r[lane]; tg1 += r[lane + 32];
    }

    // this warp's 5 support items
    #pragma unroll
    for (int j = 0; j < 5; ++j) {
        const int s = w + 4 * j;
        const int row = b * S_ + s;
        float v0 = b0, v1 = b1;
        #pragma unroll
        for (int p = 0; p < KSPLIT; ++p) {
            const float* r = g_Yp + ((size_t)p * MROWS + row) * D_;
            v0 += r[lane]; v1 += r[lane + 32];
        }
        float dot = v0 * tg0 + v1 * tg1;
        float nrm = v0 * v0 + v1 * v1;
        #pragma unroll
        for (int o = 16; o > 0; o >>= 1) {
            dot += __shfl_xor_sync(FULL, dot, o);
            nrm += __shfl_xor_sync(FULL, nrm, o);
        }
        if (lane == 0)
            sims_sh[s] = dot * rsqrtf(fmaxf(nrm, 1e-10f));
    }
    __syncthreads();

    if (w != 0) return;

    float sims[S_];
    #pragma unroll
    for (int s = 0; s < S_; ++s) sims[s] = sims_sh[s];

    float m = sims[0];
    #pragma unroll
    for (int s = 1; s < S_; ++s) m = fmaxf(m, sims[s]);
    float e[S_];
    float den = 0.f;
    #pragma unroll
    for (int s = 0; s < S_; ++s) { e[s] = expf(sims[s] - m); den += e[s]; }
    const float inv = 1.f / den;

    float pred = 0.f;
    if (lane < C_) {
        #pragma unroll
        for (int s = 0; s < S_; ++s)
            pred += e[s] * inv * onehot[((size_t)b * S_ + s) * C_ + lane];
    }

    float pv = (lane < C_) ? pred : -3.0e38f;
    float pm = pv;
    #pragma unroll
    for (int o = 16; o > 0; o >>= 1) pm = fmaxf(pm, __shfl_xor_sync(FULL, pm, o));
    float ex = (lane < C_) ? expf(pred - pm) : 0.f;
    float se = ex;
    #pragma unroll
    for (int o = 16; o > 0; o >>= 1) se += __shfl_xor_sync(FULL, se, o);
    const float lse = pm + logf(se);

    float av = pv;
    int ai = lane;
    #pragma unroll
    for (int o = 16; o > 0; o >>= 1) {
        float ov = __shfl_xor_sync(FULL, av, o);
        int oi = __shfl_xor_sync(FULL, ai, o);
        if (ov > av || (ov == av && oi < ai)) { av = ov; ai = oi; }
    }

    const int t = tylab[b];
    const float pt = __shfl_sync(FULL, pred, t);
    if (lane == 0) {
        g_res[b] = (ai == t) ? 1.f : 0.f;
        g_res[B_ + b] = -(pt - lse);
    }
}

// ---------------------------------------------------------------------------
// Final fixed-order reduction -> d_out[0]=accuracy, d_out[1]=loss
// ---------------------------------------------------------------------------
__global__ __launch_bounds__(256)
void reduce_kernel(float* __restrict__ out) {
    __shared__ float s0[B_], s1[B_];
    const int t = threadIdx.x;
    s0[t] = g_res[t];
    s1[t] = g_res[B_ + t];
    __syncthreads();
    #pragma unroll
    for (int o = 128; o > 0; o >>= 1) {
        if (t < o) { s0[t] += s0[t + o]; s1[t] += s1[t + o]; }
        __syncthreads();
    }
    if (t == 0) {
        out[0] = s0[0] * (1.f / B_);
        out[1] = s1[0] * (1.f / B_);
    }
}

extern "C" void kernel_launch(void* const* d_in, const int* in_sizes, int n_in,
                              void* d_out, int out_size) {
    const float* sup    = (const float*)d_in[0];
    const float* onehot = (const float*)d_in[1];
    const float* tgt    = (const float*)d_in[2];
    const int*   tylab  = (const int*)d_in[3];
    const float* W      = (const float*)d_in[4];
    const float* bias   = (const float*)d_in[5];
    (void)in_sizes; (void)n_in; (void)out_size;

    cudaFuncSetAttribute(gemm_kernel,
                         cudaFuncAttributeMaxDynamicSharedMemorySize, SMEM_TOTAL);

    dim3 grid(MROWS / TILE_R, KSPLIT);
    gemm_kernel<<<grid, 256, SMEM_TOTAL>>>(sup, tgt, W);
    head_kernel<<<B_, 128>>>(onehot, tylab, bias);
    reduce_kernel<<<1, 256>>>((float*)d_out);
}